// round 3
// baseline (speedup 1.0000x reference)
#include <cuda_runtime.h>

#define SNE_H 1080
#define SNE_W 1920
#define SNE_HW (SNE_H * SNE_W)
#define BX 32
#define BY 16
#define TX (BX + 2)   // 34
#define TY (BY + 2)   // 18

__device__ __forceinline__ bool f_isnan(float x) {
    return (__float_as_uint(x) & 0x7fffffffu) > 0x7f800000u;
}

// true iff x is finite and > 0 (excludes 0, inf, NaN; x is never negative here)
__device__ __forceinline__ bool f_pos_finite(float x) {
    return (__float_as_uint(x) - 1u) < 0x7f7fffffu;
}

__device__ __forceinline__ float4 make_px(int vv, int uu, float z0,
                                          float cx, float cy, float inv_fx) {
    float y = z0 * ((float)vv - cy) * inv_fx;
    const bool neg = (y <= 0.f);
    const float z = neg ? 0.f : z0;
    y = neg ? 0.f : y;
    const float x = z0 * ((float)uu - cx) * inv_fx;  // X is NOT masked (matches ref)
    const float d = __frcp_rn(z);                    // +inf where z == 0
    return make_float4(x, y, z, d);
}

__global__ void __launch_bounds__(BX * BY, 2)
sne_kernel(const float* __restrict__ depth,
           const float* __restrict__ cam,
           float* __restrict__ out)
{
    __shared__ float4 tile[TY][TX];   // (X, Y, Z_masked, D=1/Z)

    const int tx = threadIdx.x, ty = threadIdx.y;
    const int tid = ty * BX + tx;
    const int bu = blockIdx.x * BX, bv = blockIdx.y * BY;

    const float fx = cam[0], cx = cam[2], fy = cam[4], cy = cam[5];
    const float inv_fx = __frcp_rn(fx);

    // ---- Fill 34x18 halo tile (612 elems, 512 threads -> 2 rounds) ----
    {
        const int lv = tid / TX, lu = tid - lv * TX;
        const int vv = bv + lv - 1, uu = bu + lu - 1;
        float4 t = make_float4(0.f, 0.f, 0.f, 0.f);
        if ((unsigned)vv < SNE_H && (unsigned)uu < SNE_W)
            t = make_px(vv, uu, __ldg(depth + vv * SNE_W + uu), cx, cy, inv_fx);
        tile[lv][lu] = t;
    }
    if (tid < TX * TY - BX * BY) {
        const int i = tid + BX * BY;
        const int lv = i / TX, lu = i - lv * TX;
        const int vv = bv + lv - 1, uu = bu + lu - 1;
        float4 t = make_float4(0.f, 0.f, 0.f, 0.f);
        if ((unsigned)vv < SNE_H && (unsigned)uu < SNE_W)
            t = make_px(vv, uu, __ldg(depth + vv * SNE_W + uu), cx, cy, inv_fx);
        tile[lv][lu] = t;
    }
    __syncthreads();

    const int u = bu + tx, v = bv + ty;
    if (v >= SNE_H) return;   // u always < W (1920 % 32 == 0)

    const float4 c   = tile[ty + 1][tx + 1];
    const float4 n01 = tile[ty    ][tx + 1];
    const float4 n10 = tile[ty + 1][tx    ];
    const float4 n12 = tile[ty + 1][tx + 2];
    const float4 n21 = tile[ty + 2][tx + 1];

    // Gx/Gy central differences of D, scaled.
    const float nxt = fx * (n12.w - n10.w);
    const float nyt = fy * (n21.w - n01.w);

    // phi = atan(nyt/nxt) + PI; cos(phi) = -1/sqrt(1+t^2), sin(phi) = -t/sqrt(1+t^2).
    // Ternary clamp preserves NaN (comparison false for NaN).
    const float t = __fdividef(nyt, nxt);
    float at = fabsf(t);
    at = (at > 1e18f) ? 1e18f : at;
    const float rp = rsqrtf(fmaf(at, at, 1.f));
    const float a = -rp;                         // cos(phi)
    const float b = -copysignf(at * rp, t);      // sin(phi)

    // ---- 8 directional differences ----
    // Masked accumulation reduces exactly to: accumulate iff rn finite-positive.
    //   rn normal  => nxt,nyt,nzi all finite, no NaN anywhere -> accumulate
    //   rn==0      => each component is 0 (finite*0) or NaN->masked: adds 0
    //   rn==inf    => all components 0/0=NaN -> masked: adds 0
    //   rn NaN     => all masked: adds 0
    const float nn = fmaf(nxt, nxt, nyt * nyt);
    float snx = 0.f, sny = 0.f, snz = 0.f;
    const float4 nb[8] = {
        tile[ty    ][tx    ], n01, tile[ty    ][tx + 2],
        n10,                       n12,
        tile[ty + 2][tx    ], n21, tile[ty + 2][tx + 2] };
#pragma unroll
    for (int k = 0; k < 8; ++k) {
        const float Xd = c.x - nb[k].x;
        const float Yd = c.y - nb[k].y;
        const float Zd = c.z - nb[k].z;
        const float nzi = __fdividef(fmaf(nxt, Xd, nyt * Yd), Zd);
        const float rn  = rsqrtf(fmaf(nzi, nzi, nn));
        if (f_pos_finite(rn)) {
            snx = fmaf(nxt, rn, snx);
            sny = fmaf(nyt, rn, sny);
            snz = fmaf(nzi, rn, snz);
        }
    }

    // theta = -atan(s): sin = -s/sqrt(1+s^2), cos = 1/sqrt(1+s^2).
    const float s = __fdividef(fmaf(snx, a, sny * b), snz);
    float as_ = fabsf(s);
    as_ = (as_ > 1e18f) ? 1e18f : as_;
    const float rs = rsqrtf(fmaf(as_, as_, 1.f));
    const float st = -copysignf(as_ * rs, s);    // sin(theta)
    float nz = rs;                               // cos(theta); NaN iff s NaN
    float nx = st * a;
    float ny = st * b;

    const bool bad = f_isnan(nz);
    nx = bad ? 0.f : nx;
    ny = bad ? 0.f : ny;
    nz = bad ? -1.f : nz;
    const float sgn = (ny > 0.f) ? -1.f : 1.f;

    const int idx = v * SNE_W + u;
    out[idx]              = nx * sgn;
    out[SNE_HW + idx]     = ny * sgn;
    out[2 * SNE_HW + idx] = nz * sgn;
}

extern "C" void kernel_launch(void* const* d_in, const int* in_sizes, int n_in,
                              void* d_out, int out_size) {
    const float* depth = (const float*)d_in[0];
    const float* cam   = (const float*)d_in[1];
    float* out = (float*)d_out;
    dim3 blk(BX, BY);
    dim3 grd(SNE_W / BX, (SNE_H + BY - 1) / BY);
    sne_kernel<<<grd, blk>>>(depth, cam, out);
}

// round 4
// speedup vs baseline: 1.3845x; 1.3845x over previous
#include <cuda_runtime.h>

#define SNE_H 1080
#define SNE_W 1920
#define SNE_HW (SNE_H * SNE_W)
#define BX 32
#define BYT 8                  // thread rows
#define ROWS (BYT * 2)         // pixel rows per block = 16
#define TX (BX + 2)            // 34
#define TY (ROWS + 2)          // 18
#define NTHR (BX * BYT)        // 256

__device__ __forceinline__ bool f_isnan(float x) {
    return (__float_as_uint(x) & 0x7fffffffu) > 0x7f800000u;
}
// true iff x finite and > 0 (x never negative here)
__device__ __forceinline__ bool f_pos_finite(float x) {
    return (__float_as_uint(x) - 1u) < 0x7f7fffffu;
}
__device__ __forceinline__ float frcp_fast(float x) {   // 0 -> +inf, like 1/Z
    float r; asm("rcp.approx.f32 %0, %1;" : "=f"(r) : "f"(x)); return r;
}

__device__ __forceinline__ float4 make_px(int vv, int uu, float z0,
                                          float cx, float cy, float inv_fx) {
    float y = z0 * ((float)vv - cy) * inv_fx;
    const bool neg = (y <= 0.f);
    const float z = neg ? 0.f : z0;
    y = neg ? 0.f : y;
    const float x = z0 * ((float)uu - cx) * inv_fx;   // X not masked (matches ref)
    return make_float4(x, y, z, frcp_fast(z));
}

struct N3 { float x, y, z; };

// Compute one pixel's normal from the tile; center at tile[r][cc].
__device__ __forceinline__ N3 compute_px(const float4 (*__restrict__ tile)[TX],
                                         int r, int cc, float fx, float fy) {
    const float4 c   = tile[r][cc];
    const float dl = tile[r][cc - 1].w, dr = tile[r][cc + 1].w;
    const float du = tile[r - 1][cc].w, dd = tile[r + 1][cc].w;

    const float nxt = fx * (dr - dl);
    const float nyt = fy * (dd - du);

    // cos(atan(t)+pi) = -1/sqrt(1+t^2), sin = -t/sqrt(1+t^2); clamp keeps NaN.
    const float t = __fdividef(nyt, nxt);
    float at = fabsf(t);
    at = (at > 1e18f) ? 1e18f : at;
    const float rp = rsqrtf(fmaf(at, at, 1.f));
    const float a = -rp;
    const float b = -copysignf(at * rp, t);

    const float nn = fmaf(nxt, nxt, nyt * nyt);
    float snx = 0.f, sny = 0.f, snz = 0.f;
#pragma unroll
    for (int k = 0; k < 9; ++k) {
        if (k == 4) continue;
        const int dv = k / 3 - 1, du2 = k % 3 - 1;
        const float4 nb = tile[r + dv][cc + du2];
        const float Xd = c.x - nb.x;
        const float Yd = c.y - nb.y;
        const float Zd = c.z - nb.z;
        const float nzi = __fdividef(fmaf(nxt, Xd, nyt * Yd), Zd);
        const float rn  = rsqrtf(fmaf(nzi, nzi, nn));
        // Equivalent to the reference's per-component NaN-masked accumulation:
        //  rn normal => all finite, accumulate; rn∈{0,inf,NaN} => all contribs 0.
        if (f_pos_finite(rn)) {
            snx = fmaf(nxt, rn, snx);
            sny = fmaf(nyt, rn, sny);
            snz = fmaf(nzi, rn, snz);
        }
    }

    // theta = -atan(s): sin = -s/sqrt(1+s^2), cos = 1/sqrt(1+s^2).
    const float s = __fdividef(fmaf(snx, a, sny * b), snz);
    float as_ = fabsf(s);
    as_ = (as_ > 1e18f) ? 1e18f : as_;
    const float rs = rsqrtf(fmaf(as_, as_, 1.f));
    const float st = -copysignf(as_ * rs, s);
    float nz = rs;
    float nx = st * a;
    float ny = st * b;

    const bool bad = f_isnan(nz);
    nx = bad ? 0.f : nx;
    ny = bad ? 0.f : ny;
    nz = bad ? -1.f : nz;
    const float sgn = (ny > 0.f) ? -1.f : 1.f;
    return { nx * sgn, ny * sgn, nz * sgn };
}

__global__ void __launch_bounds__(NTHR)
sne_kernel(const float* __restrict__ depth,
           const float* __restrict__ cam,
           float* __restrict__ out)
{
    __shared__ float4 tile[TY][TX];   // (X, Y, Z_masked, D=1/Z)

    const int tx = threadIdx.x, ty = threadIdx.y;
    const int tid = ty * BX + tx;
    const int bu = blockIdx.x * BX, bv = blockIdx.y * ROWS;

    const float fx = cam[0], cx = cam[2], fy = cam[4], cy = cam[5];
    const float inv_fx = frcp_fast(fx);

    // ---- Fill 34x18 tile (612 elems, 256 threads -> 3 rounds) ----
#pragma unroll
    for (int base = 0; base < TX * TY; base += NTHR) {
        const int i = base + tid;
        if (i < TX * TY) {
            const int lv = i / TX, lu = i - lv * TX;
            const int vv = bv + lv - 1, uu = bu + lu - 1;
            float4 t = make_float4(0.f, 0.f, 0.f, 0.f);
            if ((unsigned)vv < SNE_H && (unsigned)uu < SNE_W)
                t = make_px(vv, uu, __ldg(depth + vv * SNE_W + uu), cx, cy, inv_fx);
            tile[lv][lu] = t;
        }
    }
    __syncthreads();

    const int u = bu + tx;
    const int v0 = bv + 2 * ty;          // pixel A row; B = v0 + 1

    const N3 pA = compute_px(tile, 2 * ty + 1, tx + 1, fx, fy);
    const N3 pB = compute_px(tile, 2 * ty + 2, tx + 1, fx, fy);

    if (v0 < SNE_H) {
        const int idx = v0 * SNE_W + u;
        out[idx]              = pA.x;
        out[SNE_HW + idx]     = pA.y;
        out[2 * SNE_HW + idx] = pA.z;
    }
    if (v0 + 1 < SNE_H) {
        const int idx = (v0 + 1) * SNE_W + u;
        out[idx]              = pB.x;
        out[SNE_HW + idx]     = pB.y;
        out[2 * SNE_HW + idx] = pB.z;
    }
}

extern "C" void kernel_launch(void* const* d_in, const int* in_sizes, int n_in,
                              void* d_out, int out_size) {
    const float* depth = (const float*)d_in[0];
    const float* cam   = (const float*)d_in[1];
    float* out = (float*)d_out;
    dim3 blk(BX, BYT);
    dim3 grd(SNE_W / BX, (SNE_H + ROWS - 1) / ROWS);
    sne_kernel<<<grd, blk>>>(depth, cam, out);
}